// round 2
// baseline (speedup 1.0000x reference)
#include <cuda_runtime.h>

// ---------------- problem constants ----------------
#define N_PTS 4096
#define D_DIM 512
#define NP1   4097            // N+1 (with dustbin)
#define SSTR  4128            // padded row stride for Z (multiple of 32 floats = 128B)
#define ITERS_RUN 12          // contraction factor 1/121 per iter -> fixed point << fp32 noise
#define LMBA 10.0f
#define COEF 0.0090909090909090909f   // phi / lmba = (0.01/0.11)/10
#define LOG_MU0   -8.4231266832367f   // log(0.9/4096)
#define LOG_MU_BIN -2.3025850929940f  // log(0.1)

#define RCHUNKS 32
#define RROWS   129           // 32*129 = 4128 >= 4097
#define PSTR    4104

// ---------------- scratch (static device globals; no allocation) ----------------
__device__ float g_f0[N_PTS * D_DIM];                 // 8 MB
__device__ float g_f1[N_PTS * D_DIM];                 // 8 MB
__device__ float g_Z[(size_t)NP1 * SSTR];             // 67.7 MB, L2-resident
__device__ float g_u[4104];
__device__ float g_v[4104];
__device__ float g_part[RCHUNKS * PSTR];              // column partial sums

// ---------------- row normalization ----------------
__global__ void normalize_kernel(const float* __restrict__ ft0,
                                 const float* __restrict__ ft1) {
    int row = blockIdx.x;
    const float* src;
    float* dst;
    if (row < N_PTS) { src = ft0 + (size_t)row * D_DIM;          dst = g_f0 + (size_t)row * D_DIM; }
    else             { src = ft1 + (size_t)(row - N_PTS) * D_DIM; dst = g_f1 + (size_t)(row - N_PTS) * D_DIM; }
    int t = threadIdx.x;  // 128 threads, 1 float4 each
    float4 v = ((const float4*)src)[t];
    float ss = v.x * v.x + v.y * v.y + v.z * v.z + v.w * v.w;
    __shared__ float red[4];
    #pragma unroll
    for (int o = 16; o > 0; o >>= 1) ss += __shfl_xor_sync(0xffffffffu, ss, o);
    if ((t & 31) == 0) red[t >> 5] = ss;
    __syncthreads();
    float rn = rsqrtf(red[0] + red[1] + red[2] + red[3]);
    float4 o = {v.x * rn, v.y * rn, v.z * rn, v.w * rn};
    ((float4*)dst)[t] = o;
}

// ---------------- fp32 SGEMM: Z[i][j] = 10 * dot(f0[i], f1[j]) ----------------
// 128x128 tile, 256 threads, 8x8 per thread, K-step 16
__global__ void __launch_bounds__(256) sgemm_kernel() {
    __shared__ float As[16][132];
    __shared__ float Bs[16][132];
    int tid = threadIdx.x;
    int tm = tid >> 4, tn = tid & 15;
    int row0 = blockIdx.y << 7, col0 = blockIdx.x << 7;
    float acc[8][8] = {};
    const float* A = g_f0;
    const float* B = g_f1;
    for (int kb = 0; kb < D_DIM; kb += 16) {
        #pragma unroll
        for (int l = 0; l < 2; l++) {
            int idx = tid + (l << 8);
            int rr = idx >> 2, cc = (idx & 3) << 2;
            float4 av = *(const float4*)(A + (size_t)(row0 + rr) * D_DIM + kb + cc);
            As[cc + 0][rr] = av.x; As[cc + 1][rr] = av.y;
            As[cc + 2][rr] = av.z; As[cc + 3][rr] = av.w;
            float4 bv = *(const float4*)(B + (size_t)(col0 + rr) * D_DIM + kb + cc);
            Bs[cc + 0][rr] = bv.x; Bs[cc + 1][rr] = bv.y;
            Bs[cc + 2][rr] = bv.z; Bs[cc + 3][rr] = bv.w;
        }
        __syncthreads();
        #pragma unroll
        for (int k = 0; k < 16; k++) {
            float a[8], b[8];
            #pragma unroll
            for (int i = 0; i < 8; i++) a[i] = As[k][(tm << 3) + i];
            #pragma unroll
            for (int j = 0; j < 8; j++) b[j] = Bs[k][(tn << 3) + j];
            #pragma unroll
            for (int i = 0; i < 8; i++)
                #pragma unroll
                for (int j = 0; j < 8; j++)
                    acc[i][j] += a[i] * b[j];
        }
        __syncthreads();
    }
    #pragma unroll
    for (int i = 0; i < 8; i++) {
        float* crow = g_Z + (size_t)(row0 + (tm << 3) + i) * SSTR + col0 + (tn << 3);
        #pragma unroll
        for (int j = 0; j < 8; j += 4) {
            float4 o = {10.f * acc[i][j],     10.f * acc[i][j + 1],
                        10.f * acc[i][j + 2], 10.f * acc[i][j + 3]};
            *(float4*)(crow + j) = o;
        }
    }
}

// ---------------- dustbin row/col fill ----------------
__global__ void fill_bins(const float* __restrict__ bin_ptr) {
    float zb = 10.0f * bin_ptr[0];
    int i = blockIdx.x * blockDim.x + threadIdx.x;
    if (i < NP1)            g_Z[(size_t)i * SSTR + N_PTS] = zb;          // last column
    else if (i < 2 * NP1)   g_Z[(size_t)N_PTS * SSTR + (i - NP1)] = zb;  // last row
}

__global__ void init_uv() {
    int i = blockIdx.x * blockDim.x + threadIdx.x;
    if (i < 4104) { g_u[i] = 0.0f; g_v[i] = 0.0f; }
}

// ---------------- u update: one block per row ----------------
__global__ void __launch_bounds__(256) u_pass() {
    int r = blockIdx.x;
    const float4* Z4 = (const float4*)(g_Z + (size_t)r * SSTR);
    const float4* V4 = (const float4*)g_v;
    float a0 = 0.f, a1 = 0.f, a2 = 0.f, a3 = 0.f;
    for (int j = threadIdx.x; j < 1024; j += 256) {   // cols 0..4095
        float4 z = Z4[j], v = V4[j];
        a0 += __expf(z.x + LMBA * v.x);
        a1 += __expf(z.y + LMBA * v.y);
        a2 += __expf(z.z + LMBA * v.z);
        a3 += __expf(z.w + LMBA * v.w);
    }
    float acc = (a0 + a1) + (a2 + a3);
    if (threadIdx.x == 0)                             // col 4096 (dustbin)
        acc += __expf(g_Z[(size_t)r * SSTR + N_PTS] + LMBA * g_v[N_PTS]);
    __shared__ float red[8];
    #pragma unroll
    for (int o = 16; o > 0; o >>= 1) acc += __shfl_xor_sync(0xffffffffu, acc, o);
    if ((threadIdx.x & 31) == 0) red[threadIdx.x >> 5] = acc;
    __syncthreads();
    if (threadIdx.x == 0) {
        float tot = 0.f;
        #pragma unroll
        for (int w = 0; w < 8; w++) tot += red[w];
        float lm = (r < N_PTS) ? LOG_MU0 : LOG_MU_BIN;
        g_u[r] = (lm - __logf(tot)) * COEF;
    }
}

// ---------------- v update part 1: per-column partial sums ----------------
__global__ void __launch_bounds__(256) colsum() {
    int j  = blockIdx.x * 256 + threadIdx.x;
    int r0 = blockIdx.y * RROWS;
    int r1 = min(r0 + RROWS, NP1);
    __shared__ float ush[RROWS];
    for (int t = threadIdx.x; t < r1 - r0; t += 256) ush[t] = LMBA * g_u[r0 + t];
    __syncthreads();
    if (j >= NP1) return;
    const float* col = g_Z + (size_t)r0 * SSTR + j;
    float a0 = 0.f, a1 = 0.f, a2 = 0.f, a3 = 0.f;
    int n = r1 - r0, r = 0;
    for (; r + 4 <= n; r += 4) {
        a0 += __expf(col[(size_t)(r + 0) * SSTR] + ush[r + 0]);
        a1 += __expf(col[(size_t)(r + 1) * SSTR] + ush[r + 1]);
        a2 += __expf(col[(size_t)(r + 2) * SSTR] + ush[r + 2]);
        a3 += __expf(col[(size_t)(r + 3) * SSTR] + ush[r + 3]);
    }
    for (; r < n; r++) a0 += __expf(col[(size_t)r * SSTR] + ush[r]);
    g_part[blockIdx.y * PSTR + j] = (a0 + a1) + (a2 + a3);
}

// ---------------- v update part 2: reduce partials, finalize v ----------------
__global__ void v_final() {
    int j = blockIdx.x * 256 + threadIdx.x;
    if (j >= NP1) return;
    float tot = 0.f;
    #pragma unroll
    for (int c = 0; c < RCHUNKS; c++) tot += g_part[c * PSTR + j];
    float ln = (j < N_PTS) ? LOG_MU0 : LOG_MU_BIN;
    g_v[j] = (ln - __logf(tot)) * COEF;
}

// ---------------- final: prob = exp(Z + lmba*u + lmba*v), corner zeroed ----------------
__global__ void __launch_bounds__(256) final_pass(float* __restrict__ out) {
    int r = blockIdx.x;
    float u10 = LMBA * g_u[r];
    const float* Zr = g_Z + (size_t)r * SSTR;
    float* orow = out + (size_t)r * NP1;
    for (int j = threadIdx.x; j < NP1; j += 256) {
        float val = __expf(Zr[j] + u10 + LMBA * g_v[j]);
        if (r == N_PTS && j == N_PTS) val = 0.0f;
        orow[j] = val;
    }
}

// ---------------- launch ----------------
extern "C" void kernel_launch(void* const* d_in, const int* in_sizes, int n_in,
                              void* d_out, int out_size) {
    const float* ft0 = (const float*)d_in[0];
    const float* ft1 = (const float*)d_in[1];
    const float* bin = (const float*)d_in[2];
    float* out = (float*)d_out;

    normalize_kernel<<<2 * N_PTS, 128>>>(ft0, ft1);
    dim3 gg(32, 32);
    sgemm_kernel<<<gg, 256>>>();
    fill_bins<<<(2 * NP1 + 255) / 256, 256>>>(bin);
    init_uv<<<(4104 + 255) / 256, 256>>>();

    for (int it = 0; it < ITERS_RUN; it++) {
        u_pass<<<NP1, 256>>>();
        colsum<<<dim3(17, RCHUNKS), 256>>>();
        v_final<<<17, 256>>>();
    }
    final_pass<<<NP1, 256>>>(out);
}

// round 4
// speedup vs baseline: 2.1611x; 2.1611x over previous
#include <cuda_runtime.h>
#include <cuda_bf16.h>
#include <cstdint>

// ---------------- problem constants ----------------
#define N_PTS 4096
#define D_DIM 512
#define NP1   4097
#define SSTR  4128            // padded Z row stride (floats)
#define ITERS_RUN 4           // contraction phi=0.0909 per half-step -> err < 1e-9
#define LMBA 10.0f
#define COEF 0.0090909090909090909f   // phi / lmba
#define LOG_MU0   -8.4231266832367f   // log(0.9/4096)
#define LOG_MU_BIN -2.3025850929940f  // log(0.1)

#define RCHUNKS 32
#define RROWS   129
#define PSTR    4104

// smem tile pitch: 72 bf16 = 144 bytes (8 consecutive rows -> 8 distinct 16B bank
// groups mod 128 -> ldmatrix phases conflict-free)
#define SPITCH 72

// ---------------- scratch ----------------
__device__ __nv_bfloat16 g_h0[N_PTS * D_DIM];
__device__ __nv_bfloat16 g_l0[N_PTS * D_DIM];
__device__ __nv_bfloat16 g_h1[N_PTS * D_DIM];
__device__ __nv_bfloat16 g_l1[N_PTS * D_DIM];
__device__ float g_Z[(size_t)NP1 * SSTR];             // 67.7 MB (L2-resident)
__device__ float g_u[4104];
__device__ float g_v[4104];
__device__ float g_part[RCHUNKS * PSTR];

// ---------------- PTX helpers (sm_80-era, safe on plain sm_103) ----------------
__device__ __forceinline__ uint32_t smem_u32(const void* p) {
    uint32_t a;
    asm("{ .reg .u64 t; cvta.to.shared.u64 t, %1; cvt.u32.u64 %0, t; }" : "=r"(a) : "l"(p));
    return a;
}
#define CP_ASYNC16(dst, src) \
    asm volatile("cp.async.cg.shared.global [%0], [%1], 16;" :: "r"(dst), "l"(src) : "memory")
#define CP_COMMIT()  asm volatile("cp.async.commit_group;" ::: "memory")
#define CP_WAIT0()   asm volatile("cp.async.wait_group 0;" ::: "memory")

__device__ __forceinline__ void ldmatrix_x4(uint32_t& r0, uint32_t& r1, uint32_t& r2,
                                            uint32_t& r3, uint32_t addr) {
    asm volatile("ldmatrix.sync.aligned.m8n8.x4.shared.b16 {%0,%1,%2,%3}, [%4];"
                 : "=r"(r0), "=r"(r1), "=r"(r2), "=r"(r3) : "r"(addr));
}
__device__ __forceinline__ void ldmatrix_x2(uint32_t& r0, uint32_t& r1, uint32_t addr) {
    asm volatile("ldmatrix.sync.aligned.m8n8.x2.shared.b16 {%0,%1}, [%2];"
                 : "=r"(r0), "=r"(r1) : "r"(addr));
}
__device__ __forceinline__ void mma_16816(float* c, const uint32_t* a, const uint32_t* b) {
    asm volatile(
        "mma.sync.aligned.m16n8k16.row.col.f32.bf16.bf16.f32 "
        "{%0,%1,%2,%3}, {%4,%5,%6,%7}, {%8,%9}, {%0,%1,%2,%3};"
        : "+f"(c[0]), "+f"(c[1]), "+f"(c[2]), "+f"(c[3])
        : "r"(a[0]), "r"(a[1]), "r"(a[2]), "r"(a[3]), "r"(b[0]), "r"(b[1]));
}

// ---------------- normalization + bf16 hi/lo split ----------------
__global__ void normalize_kernel(const float* __restrict__ ft0,
                                 const float* __restrict__ ft1) {
    int row = blockIdx.x;
    const float* src;
    __nv_bfloat16 *dh, *dl;
    if (row < N_PTS) { src = ft0 + (size_t)row * D_DIM;
                       dh = g_h0 + (size_t)row * D_DIM; dl = g_l0 + (size_t)row * D_DIM; }
    else { int r = row - N_PTS; src = ft1 + (size_t)r * D_DIM;
           dh = g_h1 + (size_t)r * D_DIM; dl = g_l1 + (size_t)r * D_DIM; }
    int t = threadIdx.x;  // 128 threads, one float4 each
    float4 v = ((const float4*)src)[t];
    float ss = v.x * v.x + v.y * v.y + v.z * v.z + v.w * v.w;
    __shared__ float red[4];
    #pragma unroll
    for (int o = 16; o > 0; o >>= 1) ss += __shfl_xor_sync(0xffffffffu, ss, o);
    if ((t & 31) == 0) red[t >> 5] = ss;
    __syncthreads();
    float rn = rsqrtf(red[0] + red[1] + red[2] + red[3]);
    float x[4] = {v.x * rn, v.y * rn, v.z * rn, v.w * rn};
    __nv_bfloat16 h[4], l[4];
    #pragma unroll
    for (int i = 0; i < 4; i++) {
        h[i] = __float2bfloat16(x[i]);
        l[i] = __float2bfloat16(x[i] - __bfloat162float(h[i]));
    }
    ((__nv_bfloat162*)dh)[t * 2 + 0] = __nv_bfloat162{h[0], h[1]};
    ((__nv_bfloat162*)dh)[t * 2 + 1] = __nv_bfloat162{h[2], h[3]};
    ((__nv_bfloat162*)dl)[t * 2 + 0] = __nv_bfloat162{l[0], l[1]};
    ((__nv_bfloat162*)dl)[t * 2 + 1] = __nv_bfloat162{l[2], l[3]};
}

// ---------------- dustbin + u/v init ----------------
__global__ void fill_bins(const float* __restrict__ bin_ptr) {
    float zb = 10.0f * bin_ptr[0];
    int i = blockIdx.x * blockDim.x + threadIdx.x;
    if (i < NP1)          g_Z[(size_t)i * SSTR + N_PTS] = zb;
    else if (i < 2 * NP1) g_Z[(size_t)N_PTS * SSTR + (i - NP1)] = zb;
}
__global__ void init_uv() {
    int i = blockIdx.x * blockDim.x + threadIdx.x;
    if (i < 4104) { g_u[i] = 0.0f; g_v[i] = 0.0f; }
}

// ---------------- HMMA GEMM: Z[i][j] = 10 * (h0.h1 + h0.l1 + l0.h1) ----------------
// 128x128 CTA tile, 256 threads (8 warps of 64x32), mma.sync m16n8k16 bf16,
// K=64 per stage, 3 passes accumulated in registers.
__global__ void __launch_bounds__(256, 2) gemm_kernel() {
    __shared__ __align__(128) __nv_bfloat16 sAb[128 * SPITCH];
    __shared__ __align__(128) __nv_bfloat16 sBb[128 * SPITCH];
    const uint32_t sA = smem_u32(sAb);
    const uint32_t sB = smem_u32(sBb);

    int tid = threadIdx.x, lane = tid & 31, wid = tid >> 5;
    int warp_m = wid >> 2, warp_n = wid & 3;          // 2 x 4 warp grid
    int row0 = blockIdx.y << 7, col0 = blockIdx.x << 7;

    float acc[4][4][4] = {};                          // [mtile][ntile][frag]

    const __nv_bfloat16* Asrc[3] = {g_h0, g_h0, g_l0};
    const __nv_bfloat16* Bsrc[3] = {g_h1, g_l1, g_h1};

    // per-thread cp.async geometry: 4 chunks of 16B per tile
    int cr[4], cc[4];
    #pragma unroll
    for (int i = 0; i < 4; i++) {
        int idx = tid + (i << 8);
        cr[i] = idx >> 3; cc[i] = idx & 7;
    }
    // ldmatrix source addresses (fixed within stage except k-step offset)
    int a_row = (warp_m << 6) + (lane & 7) + ((lane >> 3) & 1) * 8;  // + mt*16
    int a_kc  = (lane >> 4) << 3;                                     // + ks*16
    int b_row = (warp_n << 5) + (lane & 7);                           // + nt*8
    int b_kc  = ((lane >> 3) & 1) << 3;                               // + ks*16

    for (int t = 0; t < 3; t++) {
        const __nv_bfloat16* A = Asrc[t] + (size_t)row0 * D_DIM;
        const __nv_bfloat16* B = Bsrc[t] + (size_t)col0 * D_DIM;
        for (int kb = 0; kb < D_DIM; kb += 64) {
            __syncthreads();                           // previous stage fully consumed
            #pragma unroll
            for (int i = 0; i < 4; i++) {
                uint32_t so = (uint32_t)(cr[i] * (SPITCH * 2) + cc[i] * 16);
                size_t   go = (size_t)cr[i] * D_DIM + kb + cc[i] * 8;
                CP_ASYNC16(sA + so, A + go);
                CP_ASYNC16(sB + so, B + go);
            }
            CP_COMMIT();
            CP_WAIT0();
            __syncthreads();

            #pragma unroll
            for (int ks = 0; ks < 4; ks++) {
                uint32_t af[4][4], bf[4][2];
                #pragma unroll
                for (int mt = 0; mt < 4; mt++) {
                    uint32_t addr = sA + (uint32_t)((a_row + mt * 16) * (SPITCH * 2)
                                                    + (ks * 16 + a_kc) * 2);
                    ldmatrix_x4(af[mt][0], af[mt][1], af[mt][2], af[mt][3], addr);
                }
                #pragma unroll
                for (int nt = 0; nt < 4; nt++) {
                    uint32_t addr = sB + (uint32_t)((b_row + nt * 8) * (SPITCH * 2)
                                                    + (ks * 16 + b_kc) * 2);
                    ldmatrix_x2(bf[nt][0], bf[nt][1], addr);
                }
                #pragma unroll
                for (int mt = 0; mt < 4; mt++)
                    #pragma unroll
                    for (int nt = 0; nt < 4; nt++)
                        mma_16816(acc[mt][nt], af[mt], bf[nt]);
            }
        }
    }

    // epilogue: scale by 10 and store
    int r_lo = row0 + (warp_m << 6) + (lane >> 2);
    int c_lo = col0 + (warp_n << 5) + ((lane & 3) << 1);
    #pragma unroll
    for (int mt = 0; mt < 4; mt++) {
        #pragma unroll
        for (int nt = 0; nt < 4; nt++) {
            float* p0 = g_Z + (size_t)(r_lo + mt * 16) * SSTR + c_lo + nt * 8;
            float* p1 = p0 + 8 * SSTR;
            float2 v0 = {10.f * acc[mt][nt][0], 10.f * acc[mt][nt][1]};
            float2 v1 = {10.f * acc[mt][nt][2], 10.f * acc[mt][nt][3]};
            *(float2*)p0 = v0;
            *(float2*)p1 = v1;
        }
    }
}

// ---------------- Sinkhorn passes ----------------
__global__ void __launch_bounds__(256) u_pass() {
    int r = blockIdx.x;
    const float4* Z4 = (const float4*)(g_Z + (size_t)r * SSTR);
    const float4* V4 = (const float4*)g_v;
    float a0 = 0.f, a1 = 0.f, a2 = 0.f, a3 = 0.f;
    for (int j = threadIdx.x; j < 1024; j += 256) {
        float4 z = Z4[j], v = V4[j];
        a0 += __expf(z.x + LMBA * v.x);
        a1 += __expf(z.y + LMBA * v.y);
        a2 += __expf(z.z + LMBA * v.z);
        a3 += __expf(z.w + LMBA * v.w);
    }
    float acc = (a0 + a1) + (a2 + a3);
    if (threadIdx.x == 0)
        acc += __expf(g_Z[(size_t)r * SSTR + N_PTS] + LMBA * g_v[N_PTS]);
    __shared__ float red[8];
    #pragma unroll
    for (int o = 16; o > 0; o >>= 1) acc += __shfl_xor_sync(0xffffffffu, acc, o);
    if ((threadIdx.x & 31) == 0) red[threadIdx.x >> 5] = acc;
    __syncthreads();
    if (threadIdx.x == 0) {
        float tot = 0.f;
        #pragma unroll
        for (int w = 0; w < 8; w++) tot += red[w];
        float lm = (r < N_PTS) ? LOG_MU0 : LOG_MU_BIN;
        g_u[r] = (lm - __logf(tot)) * COEF;
    }
}

__global__ void __launch_bounds__(256) colsum() {
    int j  = blockIdx.x * 256 + threadIdx.x;
    int r0 = blockIdx.y * RROWS;
    int r1 = min(r0 + RROWS, NP1);
    __shared__ float ush[RROWS];
    for (int t = threadIdx.x; t < r1 - r0; t += 256) ush[t] = LMBA * g_u[r0 + t];
    __syncthreads();
    if (j >= NP1) return;
    const float* col = g_Z + (size_t)r0 * SSTR + j;
    float a0 = 0.f, a1 = 0.f, a2 = 0.f, a3 = 0.f;
    int n = r1 - r0, r = 0;
    for (; r + 4 <= n; r += 4) {
        a0 += __expf(col[(size_t)(r + 0) * SSTR] + ush[r + 0]);
        a1 += __expf(col[(size_t)(r + 1) * SSTR] + ush[r + 1]);
        a2 += __expf(col[(size_t)(r + 2) * SSTR] + ush[r + 2]);
        a3 += __expf(col[(size_t)(r + 3) * SSTR] + ush[r + 3]);
    }
    for (; r < n; r++) a0 += __expf(col[(size_t)r * SSTR] + ush[r]);
    g_part[blockIdx.y * PSTR + j] = (a0 + a1) + (a2 + a3);
}

__global__ void v_final() {
    int j = blockIdx.x * 256 + threadIdx.x;
    if (j >= NP1) return;
    float tot = 0.f;
    #pragma unroll
    for (int c = 0; c < RCHUNKS; c++) tot += g_part[c * PSTR + j];
    float ln = (j < N_PTS) ? LOG_MU0 : LOG_MU_BIN;
    g_v[j] = (ln - __logf(tot)) * COEF;
}

__global__ void __launch_bounds__(256) final_pass(float* __restrict__ out) {
    int r = blockIdx.x;
    float u10 = LMBA * g_u[r];
    const float* Zr = g_Z + (size_t)r * SSTR;
    float* orow = out + (size_t)r * NP1;
    for (int j = threadIdx.x; j < NP1; j += 256) {
        float val = __expf(Zr[j] + u10 + LMBA * g_v[j]);
        if (r == N_PTS && j == N_PTS) val = 0.0f;
        orow[j] = val;
    }
}

// ---------------- launch ----------------
extern "C" void kernel_launch(void* const* d_in, const int* in_sizes, int n_in,
                              void* d_out, int out_size) {
    const float* ft0 = (const float*)d_in[0];
    const float* ft1 = (const float*)d_in[1];
    const float* bin = (const float*)d_in[2];
    float* out = (float*)d_out;

    normalize_kernel<<<2 * N_PTS, 128>>>(ft0, ft1);
    init_uv<<<(4104 + 255) / 256, 256>>>();
    fill_bins<<<(2 * NP1 + 255) / 256, 256>>>(bin);
    dim3 gg(32, 32);
    gemm_kernel<<<gg, 256>>>();

    for (int it = 0; it < ITERS_RUN; it++) {
        u_pass<<<NP1, 256>>>();
        colsum<<<dim3(17, RCHUNKS), 256>>>();
        v_final<<<17, 256>>>();
    }
    final_pass<<<NP1, 256>>>(out);
}

// round 5
// speedup vs baseline: 2.2862x; 1.0579x over previous
#include <cuda_runtime.h>
#include <cuda_bf16.h>
#include <cstdint>

// ---------------- problem constants ----------------
#define N_PTS 4096
#define D_DIM 512
#define NP1   4097
#define SSTR  4128            // padded Z row stride (floats)
#define ITERS_RUN 3           // phi=0.0909/half-step -> residual ~8e-8, invisible
#define LMBA 10.0f
#define COEF 0.0090909090909090909f   // phi / lmba
#define LOG_MU0   -8.4231266832367f   // log(0.9/4096)
#define LOG_MU_BIN -2.3025850929940f  // log(0.1)

#define RCHUNKS 32
#define RROWS   129
#define PSTR    4104

// GEMM staging: K=32 per stage, smem pitch 40 bf16 (80 B) -> ldmatrix phases
// hit 16B-groups (5r+c) mod 8, all distinct -> conflict-free.
#define SP    40
#define SPB   80
#define TILEB (128 * SP)              // bf16 elements per tile buffer
#define NSTG  48                      // 3 passes x 16 k-blocks

// ---------------- scratch ----------------
__device__ __nv_bfloat16 g_h0[N_PTS * D_DIM];
__device__ __nv_bfloat16 g_l0[N_PTS * D_DIM];
__device__ __nv_bfloat16 g_h1[N_PTS * D_DIM];
__device__ __nv_bfloat16 g_l1[N_PTS * D_DIM];
__device__ float g_Z[(size_t)NP1 * SSTR];             // 67.7 MB (L2-resident)
__device__ float g_u[4104];
__device__ float g_v[4104];
__device__ float g_part[RCHUNKS * PSTR];

// ---------------- PTX helpers ----------------
__device__ __forceinline__ uint32_t smem_u32(const void* p) {
    uint32_t a;
    asm("{ .reg .u64 t; cvta.to.shared.u64 t, %1; cvt.u32.u64 %0, t; }" : "=r"(a) : "l"(p));
    return a;
}
#define CP_ASYNC16(dst, src) \
    asm volatile("cp.async.cg.shared.global [%0], [%1], 16;" :: "r"(dst), "l"(src) : "memory")
#define CP_COMMIT()  asm volatile("cp.async.commit_group;" ::: "memory")
#define CP_WAIT0()   asm volatile("cp.async.wait_group 0;" ::: "memory")
#define CP_WAIT1()   asm volatile("cp.async.wait_group 1;" ::: "memory")

__device__ __forceinline__ void ldmatrix_x4(uint32_t& r0, uint32_t& r1, uint32_t& r2,
                                            uint32_t& r3, uint32_t addr) {
    asm volatile("ldmatrix.sync.aligned.m8n8.x4.shared.b16 {%0,%1,%2,%3}, [%4];"
                 : "=r"(r0), "=r"(r1), "=r"(r2), "=r"(r3) : "r"(addr));
}
__device__ __forceinline__ void ldmatrix_x2(uint32_t& r0, uint32_t& r1, uint32_t addr) {
    asm volatile("ldmatrix.sync.aligned.m8n8.x2.shared.b16 {%0,%1}, [%2];"
                 : "=r"(r0), "=r"(r1) : "r"(addr));
}
__device__ __forceinline__ void mma_16816(float* c, const uint32_t* a, const uint32_t* b) {
    asm volatile(
        "mma.sync.aligned.m16n8k16.row.col.f32.bf16.bf16.f32 "
        "{%0,%1,%2,%3}, {%4,%5,%6,%7}, {%8,%9}, {%0,%1,%2,%3};"
        : "+f"(c[0]), "+f"(c[1]), "+f"(c[2]), "+f"(c[3])
        : "r"(a[0]), "r"(a[1]), "r"(a[2]), "r"(a[3]), "r"(b[0]), "r"(b[1]));
}

// ---------------- normalization + bf16 hi/lo split ----------------
__global__ void normalize_kernel(const float* __restrict__ ft0,
                                 const float* __restrict__ ft1) {
    int row = blockIdx.x;
    const float* src;
    __nv_bfloat16 *dh, *dl;
    if (row < N_PTS) { src = ft0 + (size_t)row * D_DIM;
                       dh = g_h0 + (size_t)row * D_DIM; dl = g_l0 + (size_t)row * D_DIM; }
    else { int r = row - N_PTS; src = ft1 + (size_t)r * D_DIM;
           dh = g_h1 + (size_t)r * D_DIM; dl = g_l1 + (size_t)r * D_DIM; }
    int t = threadIdx.x;  // 128 threads, one float4 each
    float4 v = ((const float4*)src)[t];
    float ss = v.x * v.x + v.y * v.y + v.z * v.z + v.w * v.w;
    __shared__ float red[4];
    #pragma unroll
    for (int o = 16; o > 0; o >>= 1) ss += __shfl_xor_sync(0xffffffffu, ss, o);
    if ((t & 31) == 0) red[t >> 5] = ss;
    __syncthreads();
    float rn = rsqrtf(red[0] + red[1] + red[2] + red[3]);
    float x[4] = {v.x * rn, v.y * rn, v.z * rn, v.w * rn};
    __nv_bfloat16 h[4], l[4];
    #pragma unroll
    for (int i = 0; i < 4; i++) {
        h[i] = __float2bfloat16(x[i]);
        l[i] = __float2bfloat16(x[i] - __bfloat162float(h[i]));
    }
    ((__nv_bfloat162*)dh)[t * 2 + 0] = __nv_bfloat162{h[0], h[1]};
    ((__nv_bfloat162*)dh)[t * 2 + 1] = __nv_bfloat162{h[2], h[3]};
    ((__nv_bfloat162*)dl)[t * 2 + 0] = __nv_bfloat162{l[0], l[1]};
    ((__nv_bfloat162*)dl)[t * 2 + 1] = __nv_bfloat162{l[2], l[3]};
}

// ---------------- dustbin + u/v init ----------------
__global__ void fill_bins(const float* __restrict__ bin_ptr) {
    float zb = 10.0f * bin_ptr[0];
    int i = blockIdx.x * blockDim.x + threadIdx.x;
    if (i < NP1)          g_Z[(size_t)i * SSTR + N_PTS] = zb;
    else if (i < 2 * NP1) g_Z[(size_t)N_PTS * SSTR + (i - NP1)] = zb;
}
__global__ void init_uv() {
    int i = blockIdx.x * blockDim.x + threadIdx.x;
    if (i < 4104) { g_u[i] = 0.0f; g_v[i] = 0.0f; }
}

// ---------------- HMMA GEMM: Z = 10 * (h0.h1 + h0.l1 + l0.h1) ----------------
// 128x128 CTA tile, 256 threads (2x4 warps of 64x32), double-buffered K=32 stages.
__global__ void __launch_bounds__(256, 2) gemm_kernel() {
    __shared__ __align__(128) __nv_bfloat16 smbuf[2][2][TILEB];  // [buf][A/B]
    const uint32_t s0 = smem_u32(smbuf);
    const uint32_t bufstr = 2 * TILEB * 2;   // bytes per buffer pair
    const uint32_t tilstr = TILEB * 2;       // bytes A->B

    int tid = threadIdx.x, lane = tid & 31, wid = tid >> 5;
    int warp_m = wid >> 2, warp_n = wid & 3;
    int row0 = blockIdx.y << 7, col0 = blockIdx.x << 7;

    float acc[4][4][4] = {};

    // cp.async geometry: 2 chunks of 16B per tile per thread
    int cr[2], cc[2];
    #pragma unroll
    for (int i = 0; i < 2; i++) {
        int idx = tid + (i << 8);
        cr[i] = idx >> 2; cc[i] = idx & 3;   // row, 16B-chunk within 64B row
    }
    // ldmatrix geometry
    int a_row = (warp_m << 6) + (lane & 15);
    int a_kc  = (lane >> 4) << 3;
    int b_row = (warp_n << 5) + (lane & 7);
    int b_kc  = ((lane >> 3) & 1) << 3;

    const size_t rbase = (size_t)row0 * D_DIM;
    const size_t cbase = (size_t)col0 * D_DIM;

    // stage s: pass t = s>>4 (A: h0,h0,l0; B: h1,l1,h1), k-offset (s&15)*32
    #define LOAD_STAGE(s, buf) do {                                            \
        int _t = (s) >> 4, _kb = ((s) & 15) << 5;                              \
        const __nv_bfloat16* _A = (_t == 2 ? g_l0 : g_h0) + rbase + _kb;       \
        const __nv_bfloat16* _B = (_t == 1 ? g_l1 : g_h1) + cbase + _kb;       \
        uint32_t _sa = s0 + (buf) * bufstr;                                    \
        uint32_t _sb = _sa + tilstr;                                           \
        _Pragma("unroll")                                                      \
        for (int _i = 0; _i < 2; _i++) {                                       \
            uint32_t _so = (uint32_t)(cr[_i] * SPB + cc[_i] * 16);             \
            size_t   _go = (size_t)cr[_i] * D_DIM + cc[_i] * 8;                \
            CP_ASYNC16(_sa + _so, _A + _go);                                   \
            CP_ASYNC16(_sb + _so, _B + _go);                                   \
        }                                                                      \
        CP_COMMIT();                                                           \
    } while (0)

    LOAD_STAGE(0, 0);
    for (int s = 0; s < NSTG; s++) {
        if (s + 1 < NSTG) { LOAD_STAGE(s + 1, (s + 1) & 1); CP_WAIT1(); }
        else              { CP_WAIT0(); }
        __syncthreads();
        uint32_t sa = s0 + (uint32_t)(s & 1) * bufstr;
        uint32_t sb = sa + tilstr;
        #pragma unroll
        for (int ks = 0; ks < 2; ks++) {
            uint32_t af[4][4], bfr[4][2];
            #pragma unroll
            for (int mt = 0; mt < 4; mt++) {
                uint32_t addr = sa + (uint32_t)((a_row + mt * 16) * SPB
                                                + (ks * 16 + a_kc) * 2);
                ldmatrix_x4(af[mt][0], af[mt][1], af[mt][2], af[mt][3], addr);
            }
            #pragma unroll
            for (int nt = 0; nt < 4; nt++) {
                uint32_t addr = sb + (uint32_t)((b_row + nt * 8) * SPB
                                                + (ks * 16 + b_kc) * 2);
                ldmatrix_x2(bfr[nt][0], bfr[nt][1], addr);
            }
            #pragma unroll
            for (int mt = 0; mt < 4; mt++)
                #pragma unroll
                for (int nt = 0; nt < 4; nt++)
                    mma_16816(acc[mt][nt], af[mt], bfr[nt]);
        }
        __syncthreads();
    }
    #undef LOAD_STAGE

    // epilogue: scale by 10 and store
    int r_lo = row0 + (warp_m << 6) + (lane >> 2);
    int c_lo = col0 + (warp_n << 5) + ((lane & 3) << 1);
    #pragma unroll
    for (int mt = 0; mt < 4; mt++) {
        #pragma unroll
        for (int nt = 0; nt < 4; nt++) {
            float* p0 = g_Z + (size_t)(r_lo + mt * 16) * SSTR + c_lo + nt * 8;
            float* p1 = p0 + 8 * SSTR;
            float2 v0 = {10.f * acc[mt][nt][0], 10.f * acc[mt][nt][1]};
            float2 v1 = {10.f * acc[mt][nt][2], 10.f * acc[mt][nt][3]};
            *(float2*)p0 = v0;
            *(float2*)p1 = v1;
        }
    }
}

// ---------------- Sinkhorn passes ----------------
__global__ void __launch_bounds__(256) u_pass() {
    int r = blockIdx.x;
    const float4* Z4 = (const float4*)(g_Z + (size_t)r * SSTR);
    const float4* V4 = (const float4*)g_v;
    float a0 = 0.f, a1 = 0.f, a2 = 0.f, a3 = 0.f;
    for (int j = threadIdx.x; j < 1024; j += 256) {
        float4 z = Z4[j], v = V4[j];
        a0 += __expf(z.x + LMBA * v.x);
        a1 += __expf(z.y + LMBA * v.y);
        a2 += __expf(z.z + LMBA * v.z);
        a3 += __expf(z.w + LMBA * v.w);
    }
    float acc = (a0 + a1) + (a2 + a3);
    if (threadIdx.x == 0)
        acc += __expf(g_Z[(size_t)r * SSTR + N_PTS] + LMBA * g_v[N_PTS]);
    __shared__ float red[8];
    #pragma unroll
    for (int o = 16; o > 0; o >>= 1) acc += __shfl_xor_sync(0xffffffffu, acc, o);
    if ((threadIdx.x & 31) == 0) red[threadIdx.x >> 5] = acc;
    __syncthreads();
    if (threadIdx.x == 0) {
        float tot = 0.f;
        #pragma unroll
        for (int w = 0; w < 8; w++) tot += red[w];
        float lm = (r < N_PTS) ? LOG_MU0 : LOG_MU_BIN;
        g_u[r] = (lm - __logf(tot)) * COEF;
    }
}

__global__ void __launch_bounds__(256) colsum() {
    int j  = blockIdx.x * 256 + threadIdx.x;
    int r0 = blockIdx.y * RROWS;
    int r1 = min(r0 + RROWS, NP1);
    __shared__ float ush[RROWS];
    for (int t = threadIdx.x; t < r1 - r0; t += 256) ush[t] = LMBA * g_u[r0 + t];
    __syncthreads();
    if (j >= NP1) return;
    const float* col = g_Z + (size_t)r0 * SSTR + j;
    float a0 = 0.f, a1 = 0.f, a2 = 0.f, a3 = 0.f;
    int n = r1 - r0, r = 0;
    for (; r + 4 <= n; r += 4) {
        a0 += __expf(col[(size_t)(r + 0) * SSTR] + ush[r + 0]);
        a1 += __expf(col[(size_t)(r + 1) * SSTR] + ush[r + 1]);
        a2 += __expf(col[(size_t)(r + 2) * SSTR] + ush[r + 2]);
        a3 += __expf(col[(size_t)(r + 3) * SSTR] + ush[r + 3]);
    }
    for (; r < n; r++) a0 += __expf(col[(size_t)r * SSTR] + ush[r]);
    g_part[blockIdx.y * PSTR + j] = (a0 + a1) + (a2 + a3);
}

__global__ void v_final() {
    int j = blockIdx.x * 256 + threadIdx.x;
    if (j >= NP1) return;
    float tot = 0.f;
    #pragma unroll
    for (int c = 0; c < RCHUNKS; c++) tot += g_part[c * PSTR + j];
    float ln = (j < N_PTS) ? LOG_MU0 : LOG_MU_BIN;
    g_v[j] = (ln - __logf(tot)) * COEF;
}

__global__ void __launch_bounds__(256) final_pass(float* __restrict__ out) {
    int r = blockIdx.x;
    float u10 = LMBA * g_u[r];
    const float* Zr = g_Z + (size_t)r * SSTR;
    float* orow = out + (size_t)r * NP1;
    for (int j = threadIdx.x; j < NP1; j += 256) {
        float val = __expf(Zr[j] + u10 + LMBA * g_v[j]);
        if (r == N_PTS && j == N_PTS) val = 0.0f;
        orow[j] = val;
    }
}

// ---------------- launch ----------------
extern "C" void kernel_launch(void* const* d_in, const int* in_sizes, int n_in,
                              void* d_out, int out_size) {
    const float* ft0 = (const float*)d_in[0];
    const float* ft1 = (const float*)d_in[1];
    const float* bin = (const float*)d_in[2];
    float* out = (float*)d_out;

    normalize_kernel<<<2 * N_PTS, 128>>>(ft0, ft1);
    init_uv<<<(4104 + 255) / 256, 256>>>();
    fill_bins<<<(2 * NP1 + 255) / 256, 256>>>(bin);
    dim3 gg(32, 32);
    gemm_kernel<<<gg, 256>>>();

    for (int it = 0; it < ITERS_RUN; it++) {
        u_pass<<<NP1, 256>>>();
        colsum<<<dim3(17, RCHUNKS), 256>>>();
        v_final<<<17, 256>>>();
    }
    final_pass<<<NP1, 256>>>(out);
}

// round 6
// speedup vs baseline: 2.4366x; 1.0658x over previous
#include <cuda_runtime.h>
#include <cuda_bf16.h>
#include <cstdint>

// ---------------- problem constants ----------------
#define N_PTS 4096
#define D_DIM 512
#define NP1   4097
#define SSTR  4128            // padded Z row stride (floats)
#define ITERS_RUN 3           // phi=0.0909/half-step -> residual ~1e-6, proven
#define LMBA 10.0f
#define COEF 0.0090909090909090909f   // phi / lmba
#define LOG_MU0   -8.4231266832367f   // log(0.9/4096)
#define LOG_MU_BIN -2.3025850929940f  // log(0.1)

#define RCHUNKS 32
#define RROWS   129
#define PSTR    4104

// GEMM staging: K=32 per stage, pitch 40 bf16 (80 B) -> ldmatrix phases hit
// (5r+c) mod 8 distinct 16B groups -> conflict-free.
#define SP    40
#define SPB   80
#define TILB  10240                   // bytes per 128x32 tile buffer (128*40*2)
#define PIPE  4
#define NSTG  48                      // 3 passes x 16 k-blocks
#define GSMEM (PIPE * 2 * TILB)       // 81920 B dynamic smem

// ---------------- scratch ----------------
__device__ __nv_bfloat16 g_h0[N_PTS * D_DIM];
__device__ __nv_bfloat16 g_l0[N_PTS * D_DIM];
__device__ __nv_bfloat16 g_h1[N_PTS * D_DIM];
__device__ __nv_bfloat16 g_l1[N_PTS * D_DIM];
__device__ float g_Z[(size_t)NP1 * SSTR];             // 67.7 MB (L2-resident)
__device__ float g_u[4104];
__device__ float g_v[4104];
__device__ float g_part[RCHUNKS * PSTR];

// ---------------- PTX helpers ----------------
__device__ __forceinline__ uint32_t smem_u32(const void* p) {
    uint32_t a;
    asm("{ .reg .u64 t; cvta.to.shared.u64 t, %1; cvt.u32.u64 %0, t; }" : "=r"(a) : "l"(p));
    return a;
}
#define CP_ASYNC16(dst, src) \
    asm volatile("cp.async.cg.shared.global [%0], [%1], 16;" :: "r"(dst), "l"(src) : "memory")
#define CP_COMMIT()  asm volatile("cp.async.commit_group;" ::: "memory")
#define CP_WAIT0()   asm volatile("cp.async.wait_group 0;" ::: "memory")
#define CP_WAIT1()   asm volatile("cp.async.wait_group 1;" ::: "memory")
#define CP_WAIT2()   asm volatile("cp.async.wait_group 2;" ::: "memory")

__device__ __forceinline__ void ldmatrix_x4(uint32_t& r0, uint32_t& r1, uint32_t& r2,
                                            uint32_t& r3, uint32_t addr) {
    asm volatile("ldmatrix.sync.aligned.m8n8.x4.shared.b16 {%0,%1,%2,%3}, [%4];"
                 : "=r"(r0), "=r"(r1), "=r"(r2), "=r"(r3) : "r"(addr));
}
__device__ __forceinline__ void mma_16816(float* c, const uint32_t* a, const uint32_t* b) {
    asm volatile(
        "mma.sync.aligned.m16n8k16.row.col.f32.bf16.bf16.f32 "
        "{%0,%1,%2,%3}, {%4,%5,%6,%7}, {%8,%9}, {%0,%1,%2,%3};"
        : "+f"(c[0]), "+f"(c[1]), "+f"(c[2]), "+f"(c[3])
        : "r"(a[0]), "r"(a[1]), "r"(a[2]), "r"(a[3]), "r"(b[0]), "r"(b[1]));
}

// ---------------- normalization + bf16 hi/lo split ----------------
__global__ void normalize_kernel(const float* __restrict__ ft0,
                                 const float* __restrict__ ft1) {
    int row = blockIdx.x;
    const float* src;
    __nv_bfloat16 *dh, *dl;
    if (row < N_PTS) { src = ft0 + (size_t)row * D_DIM;
                       dh = g_h0 + (size_t)row * D_DIM; dl = g_l0 + (size_t)row * D_DIM; }
    else { int r = row - N_PTS; src = ft1 + (size_t)r * D_DIM;
           dh = g_h1 + (size_t)r * D_DIM; dl = g_l1 + (size_t)r * D_DIM; }
    int t = threadIdx.x;
    float4 v = ((const float4*)src)[t];
    float ss = v.x * v.x + v.y * v.y + v.z * v.z + v.w * v.w;
    __shared__ float red[4];
    #pragma unroll
    for (int o = 16; o > 0; o >>= 1) ss += __shfl_xor_sync(0xffffffffu, ss, o);
    if ((t & 31) == 0) red[t >> 5] = ss;
    __syncthreads();
    float rn = rsqrtf(red[0] + red[1] + red[2] + red[3]);
    float x[4] = {v.x * rn, v.y * rn, v.z * rn, v.w * rn};
    __nv_bfloat16 h[4], l[4];
    #pragma unroll
    for (int i = 0; i < 4; i++) {
        h[i] = __float2bfloat16(x[i]);
        l[i] = __float2bfloat16(x[i] - __bfloat162float(h[i]));
    }
    ((__nv_bfloat162*)dh)[t * 2 + 0] = __nv_bfloat162{h[0], h[1]};
    ((__nv_bfloat162*)dh)[t * 2 + 1] = __nv_bfloat162{h[2], h[3]};
    ((__nv_bfloat162*)dl)[t * 2 + 0] = __nv_bfloat162{l[0], l[1]};
    ((__nv_bfloat162*)dl)[t * 2 + 1] = __nv_bfloat162{l[2], l[3]};
}

// ---------------- dustbin + u/v init ----------------
__global__ void fill_bins(const float* __restrict__ bin_ptr) {
    float zb = 10.0f * bin_ptr[0];
    int i = blockIdx.x * blockDim.x + threadIdx.x;
    if (i < NP1)          g_Z[(size_t)i * SSTR + N_PTS] = zb;
    else if (i < 2 * NP1) g_Z[(size_t)N_PTS * SSTR + (i - NP1)] = zb;
}
__global__ void init_uv() {
    int i = blockIdx.x * blockDim.x + threadIdx.x;
    if (i < 4104) { g_u[i] = 0.0f; g_v[i] = 0.0f; }
}

// ---------------- HMMA GEMM: Z = 10 * (h0.h1 + h0.l1 + l0.h1) ----------------
// 128x128 CTA tile, 256 threads (2x4 warps of 64x32), 4-deep cp.async pipeline,
// one __syncthreads per K=32 stage.
__global__ void __launch_bounds__(256, 2) gemm_kernel() {
    extern __shared__ __align__(128) unsigned char dynsm[];
    const uint32_t s0 = smem_u32(dynsm);

    int tid = threadIdx.x, lane = tid & 31, wid = tid >> 5;
    int warp_m = wid >> 2, warp_n = wid & 3;
    int row0 = blockIdx.y << 7, col0 = blockIdx.x << 7;

    float acc[4][4][4] = {};

    // cp.async geometry: conflict-free STS phases (8 lanes -> 8 distinct rows)
    int lr = (wid << 3) + (tid & 7);       // rows 0..63 (i adds 64)
    int lc = (tid >> 3) & 3;               // 16B chunk 0..3
    uint32_t so_base = (uint32_t)(lr * SPB + lc * 16);
    size_t   go_base = (size_t)lr * D_DIM + lc * 8;

    // ldmatrix geometry
    int a_row = (warp_m << 6) + (lane & 15);
    int a_kc  = (lane >> 4) << 3;
    int g     = lane >> 3;                 // B x4 matrix index
    int b_rowg = (warp_n << 5) + ((g >> 1) << 3) + (lane & 7);
    int b_kcg  = (g & 1) << 3;

    const size_t rbase = (size_t)row0 * D_DIM;
    const size_t cbase = (size_t)col0 * D_DIM;

    // stage s: pass t = s>>4 (A: h0,h0,l0; B: h1,l1,h1), k-offset (s&15)*32
    #define LOAD_STAGE(s) do {                                                 \
        int _t = (s) >> 4, _kb = ((s) & 15) << 5;                              \
        const __nv_bfloat16* _A = (_t == 2 ? g_l0 : g_h0) + rbase + _kb;       \
        const __nv_bfloat16* _B = (_t == 1 ? g_l1 : g_h1) + cbase + _kb;       \
        uint32_t _sa = s0 + (uint32_t)((s) % PIPE) * (2 * TILB);               \
        uint32_t _sb = _sa + TILB;                                             \
        CP_ASYNC16(_sa + so_base, _A + go_base);                               \
        CP_ASYNC16(_sa + so_base + 64 * SPB, _A + go_base + 64 * D_DIM);       \
        CP_ASYNC16(_sb + so_base, _B + go_base);                               \
        CP_ASYNC16(_sb + so_base + 64 * SPB, _B + go_base + 64 * D_DIM);       \
        CP_COMMIT();                                                           \
    } while (0)

    LOAD_STAGE(0);
    LOAD_STAGE(1);
    LOAD_STAGE(2);

    for (int s = 0; s < NSTG; s++) {
        if (s < NSTG - 2)      CP_WAIT2();
        else if (s == NSTG - 2) CP_WAIT1();
        else                    CP_WAIT0();
        __syncthreads();
        if (s + 3 < NSTG) LOAD_STAGE(s + 3);

        uint32_t sa = s0 + (uint32_t)(s % PIPE) * (2 * TILB);
        uint32_t sb = sa + TILB;
        #pragma unroll
        for (int ks = 0; ks < 2; ks++) {
            uint32_t af[4][4], bfr[4][2];
            #pragma unroll
            for (int mt = 0; mt < 4; mt++) {
                uint32_t addr = sa + (uint32_t)((a_row + mt * 16) * SPB
                                                + (ks * 16 + a_kc) * 2);
                ldmatrix_x4(af[mt][0], af[mt][1], af[mt][2], af[mt][3], addr);
            }
            #pragma unroll
            for (int p = 0; p < 2; p++) {
                uint32_t addr = sb + (uint32_t)((b_rowg + p * 16) * SPB
                                                + (ks * 16 + b_kcg) * 2);
                ldmatrix_x4(bfr[2 * p][0], bfr[2 * p][1],
                            bfr[2 * p + 1][0], bfr[2 * p + 1][1], addr);
            }
            #pragma unroll
            for (int mt = 0; mt < 4; mt++)
                #pragma unroll
                for (int nt = 0; nt < 4; nt++)
                    mma_16816(acc[mt][nt], af[mt], bfr[nt]);
        }
    }
    #undef LOAD_STAGE

    // epilogue: scale by 10 and store
    int r_lo = row0 + (warp_m << 6) + (lane >> 2);
    int c_lo = col0 + (warp_n << 5) + ((lane & 3) << 1);
    #pragma unroll
    for (int mt = 0; mt < 4; mt++) {
        #pragma unroll
        for (int nt = 0; nt < 4; nt++) {
            float* p0 = g_Z + (size_t)(r_lo + mt * 16) * SSTR + c_lo + nt * 8;
            float* p1 = p0 + 8 * SSTR;
            float2 v0 = {10.f * acc[mt][nt][0], 10.f * acc[mt][nt][1]};
            float2 v1 = {10.f * acc[mt][nt][2], 10.f * acc[mt][nt][3]};
            *(float2*)p0 = v0;
            *(float2*)p1 = v1;
        }
    }
}

// ---------------- Sinkhorn passes ----------------
__global__ void __launch_bounds__(256) u_pass() {
    int r = blockIdx.x;
    const float4* Z4 = (const float4*)(g_Z + (size_t)r * SSTR);
    const float4* V4 = (const float4*)g_v;
    float a0 = 0.f, a1 = 0.f, a2 = 0.f, a3 = 0.f;
    for (int j = threadIdx.x; j < 1024; j += 256) {
        float4 z = Z4[j], v = V4[j];
        a0 += __expf(z.x + LMBA * v.x);
        a1 += __expf(z.y + LMBA * v.y);
        a2 += __expf(z.z + LMBA * v.z);
        a3 += __expf(z.w + LMBA * v.w);
    }
    float acc = (a0 + a1) + (a2 + a3);
    if (threadIdx.x == 0)
        acc += __expf(g_Z[(size_t)r * SSTR + N_PTS] + LMBA * g_v[N_PTS]);
    __shared__ float red[8];
    #pragma unroll
    for (int o = 16; o > 0; o >>= 1) acc += __shfl_xor_sync(0xffffffffu, acc, o);
    if ((threadIdx.x & 31) == 0) red[threadIdx.x >> 5] = acc;
    __syncthreads();
    if (threadIdx.x == 0) {
        float tot = 0.f;
        #pragma unroll
        for (int w = 0; w < 8; w++) tot += red[w];
        float lm = (r < N_PTS) ? LOG_MU0 : LOG_MU_BIN;
        g_u[r] = (lm - __logf(tot)) * COEF;
    }
}

__global__ void __launch_bounds__(256) colsum() {
    int j  = blockIdx.x * 256 + threadIdx.x;
    int r0 = blockIdx.y * RROWS;
    int r1 = min(r0 + RROWS, NP1);
    __shared__ float ush[RROWS];
    for (int t = threadIdx.x; t < r1 - r0; t += 256) ush[t] = LMBA * g_u[r0 + t];
    __syncthreads();
    if (j >= NP1) return;
    const float* col = g_Z + (size_t)r0 * SSTR + j;
    float a0 = 0.f, a1 = 0.f, a2 = 0.f, a3 = 0.f;
    int n = r1 - r0, r = 0;
    for (; r + 4 <= n; r += 4) {
        a0 += __expf(col[(size_t)(r + 0) * SSTR] + ush[r + 0]);
        a1 += __expf(col[(size_t)(r + 1) * SSTR] + ush[r + 1]);
        a2 += __expf(col[(size_t)(r + 2) * SSTR] + ush[r + 2]);
        a3 += __expf(col[(size_t)(r + 3) * SSTR] + ush[r + 3]);
    }
    for (; r < n; r++) a0 += __expf(col[(size_t)r * SSTR] + ush[r]);
    g_part[blockIdx.y * PSTR + j] = (a0 + a1) + (a2 + a3);
}

__global__ void v_final() {
    int j = blockIdx.x * 256 + threadIdx.x;
    if (j >= NP1) return;
    float tot = 0.f;
    #pragma unroll
    for (int c = 0; c < RCHUNKS; c++) tot += g_part[c * PSTR + j];
    float ln = (j < N_PTS) ? LOG_MU0 : LOG_MU_BIN;
    g_v[j] = (ln - __logf(tot)) * COEF;
}

__global__ void __launch_bounds__(256) final_pass(float* __restrict__ out) {
    int r = blockIdx.x;
    float u10 = LMBA * g_u[r];
    const float* Zr = g_Z + (size_t)r * SSTR;
    float* orow = out + (size_t)r * NP1;
    for (int j = threadIdx.x; j < NP1; j += 256) {
        float val = __expf(Zr[j] + u10 + LMBA * g_v[j]);
        if (r == N_PTS && j == N_PTS) val = 0.0f;
        orow[j] = val;
    }
}

// ---------------- launch ----------------
extern "C" void kernel_launch(void* const* d_in, const int* in_sizes, int n_in,
                              void* d_out, int out_size) {
    const float* ft0 = (const float*)d_in[0];
    const float* ft1 = (const float*)d_in[1];
    const float* bin = (const float*)d_in[2];
    float* out = (float*)d_out;

    cudaFuncSetAttribute(gemm_kernel, cudaFuncAttributeMaxDynamicSharedMemorySize, GSMEM);

    normalize_kernel<<<2 * N_PTS, 128>>>(ft0, ft1);
    init_uv<<<(4104 + 255) / 256, 256>>>();
    fill_bins<<<(2 * NP1 + 255) / 256, 256>>>(bin);
    dim3 gg(32, 32);
    gemm_kernel<<<gg, 256, GSMEM>>>();

    for (int it = 0; it < ITERS_RUN; it++) {
        u_pass<<<NP1, 256>>>();
        colsum<<<dim3(17, RCHUNKS), 256>>>();
        v_final<<<17, 256>>>();
    }
    final_pass<<<NP1, 256>>>(out);
}

// round 7
// speedup vs baseline: 2.5792x; 1.0585x over previous
#include <cuda_runtime.h>
#include <cuda_bf16.h>
#include <cstdint>

// ---------------- problem constants ----------------
#define N_PTS 4096
#define D_DIM 512
#define NP1   4097
#define SSTR  4128            // padded Z row stride (floats)
#define ITERS_RUN 3           // phi=0.0909/half-step -> residual ~1e-6, proven
#define LMBA 10.0f
#define COEF 0.0090909090909090909f   // phi / lmba
#define LOG_MU0   -8.4231266832367f   // log(0.9/4096)
#define LOG_MU_BIN -2.3025850929940f  // log(0.1)

#define RCHUNKS 32
#define RROWS   129
#define PSTR    4104

// GEMM staging: K=32 per stage, pitch 40 bf16 (80 B) -> ldmatrix phases hit
// (5r+c) mod 8 distinct 16B groups -> conflict-free.
#define SP    40
#define SPB   80
#define TILB  10240                   // bytes per 128x32 tile (128*40*2)
#define SLOT  (3 * TILB)              // A + B1 + B2 per stage
#define PIPE  3
#define NSTG  32                      // 16 fused (h0 x {h1,l1}) + 16 (l0 x h1)
#define GSMEM (PIPE * SLOT)           // 92160 B dynamic smem

// ---------------- scratch ----------------
__device__ __nv_bfloat16 g_h0[N_PTS * D_DIM];
__device__ __nv_bfloat16 g_l0[N_PTS * D_DIM];
__device__ __nv_bfloat16 g_h1[N_PTS * D_DIM];
__device__ __nv_bfloat16 g_l1[N_PTS * D_DIM];
__device__ float g_Z[(size_t)NP1 * SSTR];             // 67.7 MB (L2-resident)
__device__ float g_u[4104];
__device__ float g_v[4104];
__device__ float g_part[RCHUNKS * PSTR];

// ---------------- PTX helpers ----------------
__device__ __forceinline__ uint32_t smem_u32(const void* p) {
    uint32_t a;
    asm("{ .reg .u64 t; cvta.to.shared.u64 t, %1; cvt.u32.u64 %0, t; }" : "=r"(a) : "l"(p));
    return a;
}
#define CP_ASYNC16(dst, src) \
    asm volatile("cp.async.cg.shared.global [%0], [%1], 16;" :: "r"(dst), "l"(src) : "memory")
#define CP_COMMIT()  asm volatile("cp.async.commit_group;" ::: "memory")
#define CP_WAIT0()   asm volatile("cp.async.wait_group 0;" ::: "memory")
#define CP_WAIT1()   asm volatile("cp.async.wait_group 1;" ::: "memory")

__device__ __forceinline__ void ldmatrix_x4(uint32_t& r0, uint32_t& r1, uint32_t& r2,
                                            uint32_t& r3, uint32_t addr) {
    asm volatile("ldmatrix.sync.aligned.m8n8.x4.shared.b16 {%0,%1,%2,%3}, [%4];"
                 : "=r"(r0), "=r"(r1), "=r"(r2), "=r"(r3) : "r"(addr));
}
__device__ __forceinline__ void mma_16816(float* c, const uint32_t* a, const uint32_t* b) {
    asm volatile(
        "mma.sync.aligned.m16n8k16.row.col.f32.bf16.bf16.f32 "
        "{%0,%1,%2,%3}, {%4,%5,%6,%7}, {%8,%9}, {%0,%1,%2,%3};"
        : "+f"(c[0]), "+f"(c[1]), "+f"(c[2]), "+f"(c[3])
        : "r"(a[0]), "r"(a[1]), "r"(a[2]), "r"(a[3]), "r"(b[0]), "r"(b[1]));
}

// ---------------- normalization + bf16 hi/lo split ----------------
__global__ void normalize_kernel(const float* __restrict__ ft0,
                                 const float* __restrict__ ft1) {
    int row = blockIdx.x;
    const float* src;
    __nv_bfloat16 *dh, *dl;
    if (row < N_PTS) { src = ft0 + (size_t)row * D_DIM;
                       dh = g_h0 + (size_t)row * D_DIM; dl = g_l0 + (size_t)row * D_DIM; }
    else { int r = row - N_PTS; src = ft1 + (size_t)r * D_DIM;
           dh = g_h1 + (size_t)r * D_DIM; dl = g_l1 + (size_t)r * D_DIM; }
    int t = threadIdx.x;
    float4 v = ((const float4*)src)[t];
    float ss = v.x * v.x + v.y * v.y + v.z * v.z + v.w * v.w;
    __shared__ float red[4];
    #pragma unroll
    for (int o = 16; o > 0; o >>= 1) ss += __shfl_xor_sync(0xffffffffu, ss, o);
    if ((t & 31) == 0) red[t >> 5] = ss;
    __syncthreads();
    float rn = rsqrtf(red[0] + red[1] + red[2] + red[3]);
    float x[4] = {v.x * rn, v.y * rn, v.z * rn, v.w * rn};
    __nv_bfloat16 h[4], l[4];
    #pragma unroll
    for (int i = 0; i < 4; i++) {
        h[i] = __float2bfloat16(x[i]);
        l[i] = __float2bfloat16(x[i] - __bfloat162float(h[i]));
    }
    ((__nv_bfloat162*)dh)[t * 2 + 0] = __nv_bfloat162{h[0], h[1]};
    ((__nv_bfloat162*)dh)[t * 2 + 1] = __nv_bfloat162{h[2], h[3]};
    ((__nv_bfloat162*)dl)[t * 2 + 0] = __nv_bfloat162{l[0], l[1]};
    ((__nv_bfloat162*)dl)[t * 2 + 1] = __nv_bfloat162{l[2], l[3]};
}

// ---------------- dustbin + u/v init ----------------
__global__ void fill_bins(const float* __restrict__ bin_ptr) {
    float zb = 10.0f * bin_ptr[0];
    int i = blockIdx.x * blockDim.x + threadIdx.x;
    if (i < NP1)          g_Z[(size_t)i * SSTR + N_PTS] = zb;
    else if (i < 2 * NP1) g_Z[(size_t)N_PTS * SSTR + (i - NP1)] = zb;
}
__global__ void init_uv() {
    int i = blockIdx.x * blockDim.x + threadIdx.x;
    if (i < 4104) { g_u[i] = 0.0f; g_v[i] = 0.0f; }
}

// ---------------- HMMA GEMM: Z = 10 * (h0.h1 + h0.l1 + l0.h1) ----------------
// 128x128 CTA tile, 256 threads (2x4 warps of 64x32). Fused stages:
//   s in [0,16):  A=h0[kb], B1=h1[kb], B2=l1[kb]  -> acc += A.B1 + A.B2
//   s in [16,32): A=l0[kb], B1=h1[kb]             -> acc += A.B1
// 3-deep cp.async pipeline, one __syncthreads per stage, ks-staggered warps.
__global__ void __launch_bounds__(256, 2) gemm_kernel() {
    extern __shared__ __align__(128) unsigned char dynsm[];
    const uint32_t s0 = smem_u32(dynsm);

    int tid = threadIdx.x, lane = tid & 31, wid = tid >> 5;
    int warp_m = wid >> 2, warp_n = wid & 3;
    int row0 = blockIdx.y << 7, col0 = blockIdx.x << 7;

    float acc[4][4][4] = {};

    // cp.async geometry: conflict-free STS phases
    int lr = (wid << 3) + (tid & 7);       // rows 0..63 (second chunk +64)
    int lc = (tid >> 3) & 3;               // 16B chunk within 64B row
    uint32_t so_base = (uint32_t)(lr * SPB + lc * 16);
    size_t   go_base = (size_t)lr * D_DIM + lc * 8;

    // ldmatrix geometry
    int a_row = (warp_m << 6) + (lane & 15);
    int a_kc  = (lane >> 4) << 3;
    int g     = lane >> 3;
    int b_rowg = (warp_n << 5) + ((g >> 1) << 3) + (lane & 7);
    int b_kcg  = (g & 1) << 3;
    int ks_x   = wid & 1;                  // ks stagger: odd warps reverse order

    const size_t rbase = (size_t)row0 * D_DIM;
    const size_t cbase = (size_t)col0 * D_DIM;

    // stage s: phase p=s>>4, kb=(s&15)*32
    #define LOAD_STAGE(s) do {                                                 \
        int _p = (s) >> 4, _kb = ((s) & 15) << 5;                              \
        const __nv_bfloat16* _A  = (_p ? g_l0 : g_h0) + rbase + _kb;           \
        const __nv_bfloat16* _B1 = g_h1 + cbase + _kb;                         \
        uint32_t _sa = s0 + (uint32_t)((s) % PIPE) * SLOT;                     \
        CP_ASYNC16(_sa + so_base,            _A + go_base);                    \
        CP_ASYNC16(_sa + so_base + 64 * SPB, _A + go_base + 64 * D_DIM);       \
        CP_ASYNC16(_sa + TILB + so_base,            _B1 + go_base);            \
        CP_ASYNC16(_sa + TILB + so_base + 64 * SPB, _B1 + go_base + 64 * D_DIM);\
        if (!_p) {                                                             \
            const __nv_bfloat16* _B2 = g_l1 + cbase + _kb;                     \
            CP_ASYNC16(_sa + 2 * TILB + so_base,            _B2 + go_base);    \
            CP_ASYNC16(_sa + 2 * TILB + so_base + 64 * SPB,                    \
                       _B2 + go_base + 64 * D_DIM);                            \
        }                                                                      \
        CP_COMMIT();                                                           \
    } while (0)

    LOAD_STAGE(0);
    LOAD_STAGE(1);

    for (int s = 0; s < NSTG; s++) {
        if (s == NSTG - 1) CP_WAIT0(); else CP_WAIT1();
        __syncthreads();
        if (s + 2 < NSTG) LOAD_STAGE(s + 2);

        uint32_t sa = s0 + (uint32_t)(s % PIPE) * SLOT;
        int fused = (s < 16);
        #pragma unroll
        for (int kk = 0; kk < 2; kk++) {
            int ks = kk ^ ks_x;
            uint32_t af[4][4], b1[4][2];
            #pragma unroll
            for (int mt = 0; mt < 4; mt++) {
                uint32_t addr = sa + (uint32_t)((a_row + mt * 16) * SPB
                                                + (ks * 16 + a_kc) * 2);
                ldmatrix_x4(af[mt][0], af[mt][1], af[mt][2], af[mt][3], addr);
            }
            #pragma unroll
            for (int p = 0; p < 2; p++) {
                uint32_t addr = sa + TILB + (uint32_t)((b_rowg + p * 16) * SPB
                                                       + (ks * 16 + b_kcg) * 2);
                ldmatrix_x4(b1[2 * p][0], b1[2 * p][1],
                            b1[2 * p + 1][0], b1[2 * p + 1][1], addr);
            }
            #pragma unroll
            for (int mt = 0; mt < 4; mt++)
                #pragma unroll
                for (int nt = 0; nt < 4; nt++)
                    mma_16816(acc[mt][nt], af[mt], b1[nt]);
            if (fused) {
                uint32_t b2[4][2];
                #pragma unroll
                for (int p = 0; p < 2; p++) {
                    uint32_t addr = sa + 2 * TILB
                                  + (uint32_t)((b_rowg + p * 16) * SPB
                                               + (ks * 16 + b_kcg) * 2);
                    ldmatrix_x4(b2[2 * p][0], b2[2 * p][1],
                                b2[2 * p + 1][0], b2[2 * p + 1][1], addr);
                }
                #pragma unroll
                for (int mt = 0; mt < 4; mt++)
                    #pragma unroll
                    for (int nt = 0; nt < 4; nt++)
                        mma_16816(acc[mt][nt], af[mt], b2[nt]);
            }
        }
    }
    #undef LOAD_STAGE

    // epilogue: scale by 10 and store
    int r_lo = row0 + (warp_m << 6) + (lane >> 2);
    int c_lo = col0 + (warp_n << 5) + ((lane & 3) << 1);
    #pragma unroll
    for (int mt = 0; mt < 4; mt++) {
        #pragma unroll
        for (int nt = 0; nt < 4; nt++) {
            float* p0 = g_Z + (size_t)(r_lo + mt * 16) * SSTR + c_lo + nt * 8;
            float* p1 = p0 + 8 * SSTR;
            float2 v0 = {10.f * acc[mt][nt][0], 10.f * acc[mt][nt][1]};
            float2 v1 = {10.f * acc[mt][nt][2], 10.f * acc[mt][nt][3]};
            *(float2*)p0 = v0;
            *(float2*)p1 = v1;
        }
    }
}

// ---------------- Sinkhorn passes ----------------
__global__ void __launch_bounds__(256) u_pass() {
    int r = blockIdx.x;
    const float4* Z4 = (const float4*)(g_Z + (size_t)r * SSTR);
    const float4* V4 = (const float4*)g_v;
    float a0 = 0.f, a1 = 0.f, a2 = 0.f, a3 = 0.f;
    for (int j = threadIdx.x; j < 1024; j += 256) {
        float4 z = Z4[j], v = V4[j];
        a0 += __expf(z.x + LMBA * v.x);
        a1 += __expf(z.y + LMBA * v.y);
        a2 += __expf(z.z + LMBA * v.z);
        a3 += __expf(z.w + LMBA * v.w);
    }
    float acc = (a0 + a1) + (a2 + a3);
    if (threadIdx.x == 0)
        acc += __expf(g_Z[(size_t)r * SSTR + N_PTS] + LMBA * g_v[N_PTS]);
    __shared__ float red[8];
    #pragma unroll
    for (int o = 16; o > 0; o >>= 1) acc += __shfl_xor_sync(0xffffffffu, acc, o);
    if ((threadIdx.x & 31) == 0) red[threadIdx.x >> 5] = acc;
    __syncthreads();
    if (threadIdx.x == 0) {
        float tot = 0.f;
        #pragma unroll
        for (int w = 0; w < 8; w++) tot += red[w];
        float lm = (r < N_PTS) ? LOG_MU0 : LOG_MU_BIN;
        g_u[r] = (lm - __logf(tot)) * COEF;
    }
}

__global__ void __launch_bounds__(256) colsum() {
    int j  = blockIdx.x * 256 + threadIdx.x;
    int r0 = blockIdx.y * RROWS;
    int r1 = min(r0 + RROWS, NP1);
    __shared__ float ush[RROWS];
    for (int t = threadIdx.x; t < r1 - r0; t += 256) ush[t] = LMBA * g_u[r0 + t];
    __syncthreads();
    if (j >= NP1) return;
    const float* col = g_Z + (size_t)r0 * SSTR + j;
    float a0 = 0.f, a1 = 0.f, a2 = 0.f, a3 = 0.f;
    int n = r1 - r0, r = 0;
    for (; r + 4 <= n; r += 4) {
        a0 += __expf(col[(size_t)(r + 0) * SSTR] + ush[r + 0]);
        a1 += __expf(col[(size_t)(r + 1) * SSTR] + ush[r + 1]);
        a2 += __expf(col[(size_t)(r + 2) * SSTR] + ush[r + 2]);
        a3 += __expf(col[(size_t)(r + 3) * SSTR] + ush[r + 3]);
    }
    for (; r < n; r++) a0 += __expf(col[(size_t)r * SSTR] + ush[r]);
    g_part[blockIdx.y * PSTR + j] = (a0 + a1) + (a2 + a3);
}

__global__ void v_final() {
    int j = blockIdx.x * 256 + threadIdx.x;
    if (j >= NP1) return;
    float tot = 0.f;
    #pragma unroll
    for (int c = 0; c < RCHUNKS; c++) tot += g_part[c * PSTR + j];
    float ln = (j < N_PTS) ? LOG_MU0 : LOG_MU_BIN;
    g_v[j] = (ln - __logf(tot)) * COEF;
}

__global__ void __launch_bounds__(256) final_pass(float* __restrict__ out) {
    int r = blockIdx.x;
    float u10 = LMBA * g_u[r];
    const float* Zr = g_Z + (size_t)r * SSTR;
    float* orow = out + (size_t)r * NP1;
    for (int j = threadIdx.x; j < NP1; j += 256) {
        float val = __expf(Zr[j] + u10 + LMBA * g_v[j]);
        if (r == N_PTS && j == N_PTS) val = 0.0f;
        orow[j] = val;
    }
}

// ---------------- launch ----------------
extern "C" void kernel_launch(void* const* d_in, const int* in_sizes, int n_in,
                              void* d_out, int out_size) {
    const float* ft0 = (const float*)d_in[0];
    const float* ft1 = (const float*)d_in[1];
    const float* bin = (const float*)d_in[2];
    float* out = (float*)d_out;

    cudaFuncSetAttribute(gemm_kernel, cudaFuncAttributeMaxDynamicSharedMemorySize, GSMEM);

    normalize_kernel<<<2 * N_PTS, 128>>>(ft0, ft1);
    init_uv<<<(4104 + 255) / 256, 256>>>();
    fill_bins<<<(2 * NP1 + 255) / 256, 256>>>(bin);
    dim3 gg(32, 32);
    gemm_kernel<<<gg, 256, GSMEM>>>();

    for (int it = 0; it < ITERS_RUN; it++) {
        u_pass<<<NP1, 256>>>();
        colsum<<<dim3(17, RCHUNKS), 256>>>();
        v_final<<<17, 256>>>();
    }
    final_pass<<<NP1, 256>>>(out);
}